// round 4
// baseline (speedup 1.0000x reference)
#include <cuda_runtime.h>
#include <cuda_bf16.h>
#include <cstdint>

#define NCTA 128
#define NTHR 256
#define B_   128
#define T_   800
#define H_   256
#define U_   64
#define KMIX 10
#define GMIX 20
#define A_   64
#define SSTRIDE 580
#define TB_  (T_*B_)

// ------------------------- persistent device state ---------------------------
__device__ float g_h1[2][B_*H_];
__device__ float g_h2[2][B_*H_];
__device__ float g_h3[2][B_*H_];
__device__ float g_w[B_*A_];
__device__ float g_hist[(size_t)T_*B_*H_];
__device__ unsigned g_arrive;
__device__ volatile unsigned g_epoch;

__device__ __forceinline__ float sigmf(float x) { return 1.0f/(1.0f+expf(-x)); }

// ------------------------- grid barrier (epoch counting) ---------------------
__device__ __forceinline__ void gbar(unsigned e) {
  __syncthreads();
  if (threadIdx.x == 0) {
    __threadfence();
    unsigned v = atomicAdd(&g_arrive, 1u);
    if (v == e*(unsigned)NCTA - 1u) {
      atomicExch((unsigned*)&g_epoch, e);   // strong GPU-scope release
    } else {
      while (g_epoch < e) { __nanosleep(32); }
    }
    __threadfence();
  }
  __syncthreads();
}

// ------------------------- LSTM phase ----------------------------------------
// CTA tile: rows [b0,b0+32), units [u0,u0+8), all 4 gates (32 gate cols).
// Input layout: [x(3) | w(64) | hmid(256 iff KIN=323) | hrec(256)]
template<int KIN>
__device__ __forceinline__ void lstm_phase(
    float* __restrict__ sin, float* __restrict__ gsm, float* __restrict__ c_sm,
    int t, int b0, int u0, int tid,
    const float* __restrict__ x,
    const float* __restrict__ hmid,
    const float* __restrict__ hrec,
    const float* __restrict__ Wih, const float* __restrict__ Whh,
    const float* __restrict__ bih, const float* __restrict__ bhh,
    float* __restrict__ hout, float* __restrict__ histp)
{
  const int KTOT = KIN + 256;
  // ---- stage inputs into smem ----
  {
    int r = 0, k = tid;
    const int total = 32 * KTOT;
    for (int idx = tid; idx < total; idx += NTHR) {
      int b = b0 + r;
      float v;
      if (k < 3)                      v = __ldg(&x[(b*T_ + t)*3 + k]);
      else if (k < 67)                v = __ldcg(&g_w[b*A_ + (k-3)]);
      else if (KIN == 323 && k < KIN) v = __ldcg(&hmid[b*H_ + (k-67)]);
      else                            v = __ldcg(&hrec[b*H_ + (k-KIN)]);
      sin[r*SSTRIDE + k] = v;
      k += NTHR;
      if (k >= KTOT) { k -= KTOT; r++; }
    }
  }
  __syncthreads();

  // ---- GEMM: each thread = 1 row x 4 gate-cols ----
  const int tx   = tid & 7;         // 8 col groups
  const int row  = tid >> 3;        // 32 rows
  const int gate = tx >> 1;
  const int coff = (tx & 1) * 4;
  const int col  = gate*H_ + u0 + coff;
  const float* srow = sin + row*SSTRIDE;

  float a0=0.f, a1=0.f, a2=0.f, a3=0.f;
  {
    const float4* W4 = reinterpret_cast<const float4*>(Wih) + (col >> 2);
    #pragma unroll 4
    for (int k = 0; k < KIN; ++k) {
      float4 wv = W4[(size_t)k*256];
      float v = srow[k];
      a0 = fmaf(v, wv.x, a0); a1 = fmaf(v, wv.y, a1);
      a2 = fmaf(v, wv.z, a2); a3 = fmaf(v, wv.w, a3);
    }
  }
  {
    const float4* W4 = reinterpret_cast<const float4*>(Whh) + (col >> 2);
    const float* srec = srow + KIN;
    #pragma unroll 4
    for (int k = 0; k < 256; ++k) {
      float4 wv = W4[(size_t)k*256];
      float v = srec[k];
      a0 = fmaf(v, wv.x, a0); a1 = fmaf(v, wv.y, a1);
      a2 = fmaf(v, wv.z, a2); a3 = fmaf(v, wv.w, a3);
    }
  }
  {
    float4 bi = *reinterpret_cast<const float4*>(bih + col);
    float4 bh = *reinterpret_cast<const float4*>(bhh + col);
    a0 += bi.x + bh.x; a1 += bi.y + bh.y;
    a2 += bi.z + bh.z; a3 += bi.w + bh.w;
  }
  {
    float* gp = gsm + row*32 + gate*8 + coff;
    gp[0]=a0; gp[1]=a1; gp[2]=a2; gp[3]=a3;
  }
  __syncthreads();

  // ---- cell update (gate order i,f,g,o) ----
  {
    const int r = tid >> 3, u = tid & 7;
    const float* gr = gsm + r*32;
    float ii = sigmf(gr[u]);
    float ff = sigmf(gr[8 + u]);
    float gg = tanhf(gr[16 + u]);
    float oo = sigmf(gr[24 + u]);
    float cv = ff * c_sm[tid] + ii * gg;
    c_sm[tid] = cv;
    float hv = oo * tanhf(cv);
    int gb = (b0 + r)*H_ + u0 + u;
    __stcg(&hout[gb], hv);
    if (histp) histp[gb] = hv;
  }
  __syncthreads();
}

// ------------------------- reset (per launch) --------------------------------
__global__ void reset_kernel() {
  g_arrive = 0u;
  g_epoch  = 0u;
}

// ------------------------- main persistent kernel ----------------------------
__global__ void __launch_bounds__(NTHR, 1) main_kernel(
    const float* __restrict__ x,  const int* __restrict__ cc,
    const float* __restrict__ Wih1, const float* __restrict__ Whh1,
    const float* __restrict__ bih1, const float* __restrict__ bhh1,
    const float* __restrict__ Wih2, const float* __restrict__ Whh2,
    const float* __restrict__ bih2, const float* __restrict__ bhh2,
    const float* __restrict__ Wih3, const float* __restrict__ Whh3,
    const float* __restrict__ bih3, const float* __restrict__ bhh3,
    const float* __restrict__ Ww,   const float* __restrict__ bw)
{
  extern __shared__ float sm[];
  float* sin   = sm;                    // 32*SSTRIDE
  float* gsm   = sin + 32*SSTRIDE;      // 1024
  float* c1    = gsm + 1024;            // 256
  float* c2    = c1 + 256;              // 256
  float* c3    = c2 + 256;              // 256
  float* h1row = c3 + 256;              // 256
  float* win   = h1row + 256;           // 32 (alpha 0..9 | beta 10..19 | kraw 20..29)
  float* kap   = win + 32;              // 16
  float* Phi   = kap + 16;              // 64
  int*   cidx  = (int*)(Phi + 64);      // 64

  const int tid  = threadIdx.x;
  const int cta  = blockIdx.x;
  const int rt   = cta >> 5, ut = cta & 31;
  const int b0   = rt * 32, u0 = ut * 8;
  const int brow = cta;                 // window-phase row

  // ---- per-launch state init ----
  c1[tid]=0.f; c2[tid]=0.f; c3[tid]=0.f;
  if (tid < 16)  kap[tid] = 0.f;
  if (tid < 64)  cidx[tid] = __ldg(&cc[brow*U_ + tid]);
  __stcg(&g_h1[0][brow*H_ + tid], 0.f);
  __stcg(&g_h2[0][brow*H_ + tid], 0.f);
  __stcg(&g_h3[0][brow*H_ + tid], 0.f);
  if (tid < 64) __stcg(&g_w[brow*A_ + tid], 1.0f);

  unsigned ep = 1;
  gbar(ep++);

  for (int t = 0; t < T_; ++t) {
    const int p = t & 1;

    // ---- phase A: LSTM1 ----
    lstm_phase<67>(sin, gsm, c1, t, b0, u0, tid,
                   x, g_h1[p], g_h1[p],
                   Wih1, Whh1, bih1, bhh1,
                   g_h1[1-p], (float*)0);
    gbar(ep++);

    // ---- phase B: attention window (CTA brow handles row brow) ----
    {
      const float* h1g = g_h1[1-p];
      for (int i = tid; i < 256; i += NTHR) h1row[i] = __ldcg(&h1g[brow*H_ + i]);
      __syncthreads();
      // 32 groups of 8 lanes; groups 30,31 compute a dummy column (jc=0) so
      // that every lane of every warp reaches the shuffles (deadlock fix).
      int j = tid >> 3, l = tid & 7;
      int jc = (j < 30) ? j : 0;
      float s = 0.f;
      for (int k = l; k < 256; k += 8) s = fmaf(h1row[k], __ldg(&Ww[k*30 + jc]), s);
      s += __shfl_xor_sync(0xffffffffu, s, 4);
      s += __shfl_xor_sync(0xffffffffu, s, 2);
      s += __shfl_xor_sync(0xffffffffu, s, 1);
      if (l == 0 && j < 30) win[j] = expf(s + __ldg(&bw[j]));
      __syncthreads();
      if (tid < KMIX) kap[tid] += 0.1f * win[20 + tid];
      __syncthreads();
      if (tid < U_) {
        float u = (float)tid;
        float ph = 0.f;
        #pragma unroll
        for (int k = 0; k < KMIX; ++k) {
          float d = kap[k] - u;
          ph += win[k] * expf(-win[10 + k] * d * d);
        }
        Phi[tid] = ph;
      }
      __syncthreads();
      if (tid < A_) {
        float s2 = 0.f;
        #pragma unroll 4
        for (int u = 0; u < U_; ++u)
          if (cidx[u] == tid) s2 += Phi[u];
        __stcg(&g_w[brow*A_ + tid], s2);
      }
    }
    gbar(ep++);

    // ---- phase C: LSTM2 ----
    lstm_phase<323>(sin, gsm, c2, t, b0, u0, tid,
                    x, g_h1[1-p], g_h2[p],
                    Wih2, Whh2, bih2, bhh2,
                    g_h2[1-p], (float*)0);
    gbar(ep++);

    // ---- phase D: LSTM3 (+ history) ----
    lstm_phase<323>(sin, gsm, c3, t, b0, u0, tid,
                    x, g_h2[1-p], g_h3[p],
                    Wih3, Whh3, bih3, bhh3,
                    g_h3[1-p], &g_hist[(size_t)t * B_ * H_]);
    // no barrier needed before next phase A: D(t) and A(t+1) touch disjoint
    // buffers, and two barriers separate D(t) from any reader of its outputs.
  }
}

// ------------------------- MDN heads -----------------------------------------
#define PHEAD 8
__global__ void __launch_bounds__(128) heads_kernel(
    const float* __restrict__ We,   const float* __restrict__ be,
    const float* __restrict__ Wpi,  const float* __restrict__ bpi,
    const float* __restrict__ Wmu1, const float* __restrict__ bmu1,
    const float* __restrict__ Wmu2, const float* __restrict__ bmu2,
    const float* __restrict__ Ws1,  const float* __restrict__ bs1,
    const float* __restrict__ Ws2,  const float* __restrict__ bs2,
    const float* __restrict__ Wrho, const float* __restrict__ brho,
    float* __restrict__ out)
{
  __shared__ float hs[PHEAD*H_];
  __shared__ float raw[PHEAD][128];
  __shared__ float stat[PHEAD][2];
  const int p0  = blockIdx.x * PHEAD;
  const int tid = threadIdx.x;

  for (int i = tid; i < PHEAD*H_; i += 128)
    hs[i] = g_hist[(size_t)p0*H_ + i];
  __syncthreads();

  const int j = tid;
  if (j < 121) {
    const float* W; int stride, cs; float bias;
    if (j == 0)      { W = We;   stride = 1;  cs = 0;     bias = __ldg(&be[0]);    }
    else if (j < 21) { W = Wpi;  stride = 20; cs = j-1;   bias = __ldg(&bpi[cs]);  }
    else if (j < 41) { W = Wmu1; stride = 20; cs = j-21;  bias = __ldg(&bmu1[cs]); }
    else if (j < 61) { W = Wmu2; stride = 20; cs = j-41;  bias = __ldg(&bmu2[cs]); }
    else if (j < 81) { W = Ws1;  stride = 20; cs = j-61;  bias = __ldg(&bs1[cs]);  }
    else if (j < 101){ W = Ws2;  stride = 20; cs = j-81;  bias = __ldg(&bs2[cs]);  }
    else             { W = Wrho; stride = 20; cs = j-101; bias = __ldg(&brho[cs]); }
    float acc[PHEAD];
    #pragma unroll
    for (int r = 0; r < PHEAD; ++r) acc[r] = 0.f;
    #pragma unroll 4
    for (int k = 0; k < H_; ++k) {
      float wv = __ldg(&W[k*stride + cs]);
      #pragma unroll
      for (int r = 0; r < PHEAD; ++r) acc[r] = fmaf(hs[r*H_ + k], wv, acc[r]);
    }
    #pragma unroll
    for (int r = 0; r < PHEAD; ++r) raw[r][j] = acc[r] + bias;
  }
  __syncthreads();

  if (tid < PHEAD) {
    float m = -1e30f;
    for (int g = 1; g < 21; ++g) m = fmaxf(m, raw[tid][g]);
    float s = 0.f;
    for (int g = 1; g < 21; ++g) s += expf(raw[tid][g] - m);
    stat[tid][0] = m; stat[tid][1] = s;
  }
  __syncthreads();

  if (j < 121) {
    const int blk = (j == 0) ? -1 : (j-1)/20;
    const int g   = (j == 0) ? 0  : (j-1)%20;
    #pragma unroll
    for (int r = 0; r < PHEAD; ++r) {
      size_t p = (size_t)(p0 + r);
      float v = raw[r][j];
      if (j == 0) {
        out[p] = 1.0f / (1.0f + expf(v));
      } else {
        float o;
        if      (blk == 0) o = expf(v - stat[r][0]) / stat[r][1];
        else if (blk <= 2) o = v;
        else if (blk <= 4) o = expf(v);
        else               o = tanhf(v);
        out[(size_t)TB_ + (size_t)blk * (TB_*(size_t)GMIX) + p*GMIX + g] = o;
      }
    }
  }
}

// ------------------------- launch --------------------------------------------
extern "C" void kernel_launch(void* const* d_in, const int* in_sizes, int n_in,
                              void* d_out, int out_size) {
  const float* x    = (const float*)d_in[0];
  const int*   cc   = (const int*)  d_in[1];
  const float* Wih1 = (const float*)d_in[2];
  const float* Whh1 = (const float*)d_in[3];
  const float* bih1 = (const float*)d_in[4];
  const float* bhh1 = (const float*)d_in[5];
  const float* Wih2 = (const float*)d_in[6];
  const float* Whh2 = (const float*)d_in[7];
  const float* bih2 = (const float*)d_in[8];
  const float* bhh2 = (const float*)d_in[9];
  const float* Wih3 = (const float*)d_in[10];
  const float* Whh3 = (const float*)d_in[11];
  const float* bih3 = (const float*)d_in[12];
  const float* bhh3 = (const float*)d_in[13];
  const float* Ww   = (const float*)d_in[14];
  const float* bw   = (const float*)d_in[15];
  const float* We   = (const float*)d_in[16];
  const float* be   = (const float*)d_in[17];
  const float* Wpi  = (const float*)d_in[18];
  const float* bpi  = (const float*)d_in[19];
  const float* Wmu1 = (const float*)d_in[20];
  const float* bmu1 = (const float*)d_in[21];
  const float* Wmu2 = (const float*)d_in[22];
  const float* bmu2 = (const float*)d_in[23];
  const float* Ws1  = (const float*)d_in[24];
  const float* bs1  = (const float*)d_in[25];
  const float* Ws2  = (const float*)d_in[26];
  const float* bs2  = (const float*)d_in[27];
  const float* Wrho = (const float*)d_in[28];
  const float* brho = (const float*)d_in[29];
  float* out = (float*)d_out;

  const int smem_bytes = (32*SSTRIDE + 1024 + 3*256 + 256 + 32 + 16 + 64 + 64) * 4;
  cudaFuncSetAttribute(main_kernel, cudaFuncAttributeMaxDynamicSharedMemorySize, smem_bytes);

  reset_kernel<<<1, 1>>>();
  main_kernel<<<NCTA, NTHR, smem_bytes>>>(
      x, cc, Wih1, Whh1, bih1, bhh1, Wih2, Whh2, bih2, bhh2,
      Wih3, Whh3, bih3, bhh3, Ww, bw);
  heads_kernel<<<TB_/PHEAD, 128>>>(
      We, be, Wpi, bpi, Wmu1, bmu1, Wmu2, bmu2,
      Ws1, bs1, Ws2, bs2, Wrho, brho, out);
}

// round 7
// speedup vs baseline: 4.3105x; 4.3105x over previous
#include <cuda_runtime.h>
#include <cuda_bf16.h>
#include <cstdint>

#define NCTA 128
#define NTHR 256
#define B_   128
#define T_   800
#define H_   256
#define U_   64
#define KMIX 10
#define GMIX 20
#define A_   64
#define TB_  (T_*B_)

// smem layout (float offsets)
#define OFF_W1   0        // [323*8]
#define OFF_W2   2584     // [579*8]
#define OFF_W3   7216     // [579*8]
#define OFF_B    11848    // [24]
#define OFF_BW   11872    // [128*68]
#define OFF_H0   20576    // [128*132]
#define OFF_H1   37472    // [128*132]
#define OFF_G    54368    // [128*8]
#define OFF_C    55392    // [3*256]
#define OFF_HR   56160    // [256]
#define OFF_WIN  56416    // [32]
#define OFF_KAP  56448    // [16]
#define OFF_PHI  56464    // [64]
#define OFF_CIDX 56528    // [64] ints
#define SMEM_FLOATS 56592
#define SMEM_BYTES (SMEM_FLOATS*4)

// ------------------------- persistent device state ---------------------------
__device__ __align__(16) float g_h1[2][B_*H_];
__device__ __align__(16) float g_h2[2][B_*H_];
__device__ __align__(16) float g_h3[2][B_*H_];
__device__ __align__(16) float g_w[B_*A_];
__device__ __align__(16) float g_hist[(size_t)T_*B_*H_];
__device__ unsigned g_arrive;
__device__ volatile unsigned g_epoch;

__device__ __forceinline__ float sigmf(float x) { return 1.0f/(1.0f+expf(-x)); }

// ------------------------- cp.async helpers ----------------------------------
__device__ __forceinline__ unsigned smem_u32(const void* p) {
  return (unsigned)__cvta_generic_to_shared(p);
}
__device__ __forceinline__ void cpa16(unsigned dst, const float* src) {
  asm volatile("cp.async.cg.shared.global [%0], [%1], 16;\n" :: "r"(dst), "l"(src));
}
#define CP_COMMIT  asm volatile("cp.async.commit_group;\n")
#define CP_WAIT(n) asm volatile("cp.async.wait_group %0;\n" :: "n"(n))

// ------------------------- grid barrier (epoch counting) ---------------------
__device__ __forceinline__ void gbar(unsigned e) {
  __syncthreads();
  if (threadIdx.x == 0) {
    __threadfence();
    unsigned v = atomicAdd(&g_arrive, 1u);
    if (v == e*(unsigned)NCTA - 1u) {
      atomicExch((unsigned*)&g_epoch, e);
    } else {
      while (g_epoch < e) { __nanosleep(32); }
    }
    __threadfence();
  }
  __syncthreads();
}

// ------------------------- staging -------------------------------------------
// stage one 128-wide K chunk of an h-matrix [128 rows x 256] into buf[128][132]
__device__ __forceinline__ void stage_h(float* buf, const float* src, int k0, int tid) {
  #pragma unroll
  for (int n = 0; n < 16; ++n) {
    int i = tid + n*NTHR;
    int r = i >> 5, kq = i & 31;
    cpa16(smem_u32(buf + r*132 + kq*4), src + r*256 + k0 + kq*4);
  }
}
// stage attention-window vector w [128 rows x 64] into bufW[128][68]
__device__ __forceinline__ void stage_w(float* buf, int tid) {
  #pragma unroll
  for (int n = 0; n < 8; ++n) {
    int i = tid + n*NTHR;
    int r = i >> 4, kq = i & 15;
    cpa16(smem_u32(buf + r*68 + kq*4), g_w + r*64 + kq*4);
  }
}

// ------------------------- 128-k FMA chunk -----------------------------------
__device__ __forceinline__ void chunk_fma(
    float& a0, float& a1, float& a2, float& a3,
    const float* __restrict__ ar,   // act row ptr (buf + row*132)
    const float* __restrict__ wk)   // weight ptr  (wsm + k0*8 + cg*4)
{
  #pragma unroll 4
  for (int q = 0; q < 32; ++q) {
    float4 av = *(const float4*)(ar + q*4);
    float4 w0 = *(const float4*)(wk + (q*4+0)*8);
    a0=fmaf(av.x,w0.x,a0); a1=fmaf(av.x,w0.y,a1); a2=fmaf(av.x,w0.z,a2); a3=fmaf(av.x,w0.w,a3);
    float4 w1 = *(const float4*)(wk + (q*4+1)*8);
    a0=fmaf(av.y,w1.x,a0); a1=fmaf(av.y,w1.y,a1); a2=fmaf(av.y,w1.z,a2); a3=fmaf(av.y,w1.w,a3);
    float4 w2 = *(const float4*)(wk + (q*4+2)*8);
    a0=fmaf(av.z,w2.x,a0); a1=fmaf(av.z,w2.y,a1); a2=fmaf(av.z,w2.z,a2); a3=fmaf(av.z,w2.w,a3);
    float4 w3 = *(const float4*)(wk + (q*4+3)*8);
    a0=fmaf(av.w,w3.x,a0); a1=fmaf(av.w,w3.y,a1); a2=fmaf(av.w,w3.z,a2); a3=fmaf(av.w,w3.w,a3);
  }
}

// ------------------------- LSTM phase ----------------------------------------
// CTA owns units {2*cta, 2*cta+1} x all 128 rows. Virtual input:
// [x(3) | w(64) | hA(256) | hB(256 iff HASB)], weights preloaded in wsmL[k][8]
// smem col order per k: [i0,i1,f0,f1,g0,g1,o0,o1].
template<bool HASB>
__device__ __forceinline__ void lstm_phase(
    float* __restrict__ sm,
    const float* __restrict__ wsmL, const float* __restrict__ bsmL,
    float* __restrict__ csmL,
    int t, int cta, int tid,
    const float* __restrict__ x,
    const float* __restrict__ hA, const float* __restrict__ hB,
    float* __restrict__ hout, float* __restrict__ histp)
{
  float* bufW = sm + OFF_BW;
  float* b0   = sm + OFF_H0;
  float* b1   = sm + OFF_H1;
  float* gsm  = sm + OFF_G;
  const int row = tid >> 1, cg = tid & 1;

  stage_w(bufW, tid);            CP_COMMIT;   // G1
  stage_h(b0, hA, 0, tid);       CP_COMMIT;   // G2

  float a0=0.f, a1=0.f, a2=0.f, a3=0.f;
  // x part (k = 0..2), x read-only -> L1-safe __ldg
  {
    const float* xr = x + (row*T_ + t)*3;
    float xv0=__ldg(xr), xv1=__ldg(xr+1), xv2=__ldg(xr+2);
    const float* wk = wsmL + cg*4;
    float4 w0=*(const float4*)(wk), w1=*(const float4*)(wk+8), w2=*(const float4*)(wk+16);
    a0=fmaf(xv0,w0.x,a0); a1=fmaf(xv0,w0.y,a1); a2=fmaf(xv0,w0.z,a2); a3=fmaf(xv0,w0.w,a3);
    a0=fmaf(xv1,w1.x,a0); a1=fmaf(xv1,w1.y,a1); a2=fmaf(xv1,w1.z,a2); a3=fmaf(xv1,w1.w,a3);
    a0=fmaf(xv2,w2.x,a0); a1=fmaf(xv2,w2.y,a1); a2=fmaf(xv2,w2.z,a2); a3=fmaf(xv2,w2.w,a3);
  }
  CP_WAIT(1); __syncthreads();   // G1 (bufW) done
  // w segment (k = 3..66)
  {
    const float* ar = bufW + row*68;
    const float* wk = wsmL + 3*8 + cg*4;
    #pragma unroll 8
    for (int k = 0; k < 64; ++k) {
      float av = ar[k];
      float4 wv = *(const float4*)(wk + k*8);
      a0=fmaf(av,wv.x,a0); a1=fmaf(av,wv.y,a1); a2=fmaf(av,wv.z,a2); a3=fmaf(av,wv.w,a3);
    }
  }
  stage_h(b1, hA, 128, tid); CP_COMMIT;   // G3
  CP_WAIT(1); __syncthreads();            // G2 (b0 = hA[0:128)) done
  chunk_fma(a0,a1,a2,a3, b0 + row*132, wsmL + 67*8 + cg*4);
  __syncthreads();                        // everyone done reading b0
  if (HASB) { stage_h(b0, hB, 0, tid); CP_COMMIT; }   // G4
  CP_WAIT(HASB ? 1 : 0); __syncthreads(); // G3 (b1 = hA[128:256)) done
  chunk_fma(a0,a1,a2,a3, b1 + row*132, wsmL + 195*8 + cg*4);
  if (HASB) {
    __syncthreads();                      // done reading b1
    stage_h(b1, hB, 128, tid); CP_COMMIT; // G5
    CP_WAIT(1); __syncthreads();          // G4 done
    chunk_fma(a0,a1,a2,a3, b0 + row*132, wsmL + 323*8 + cg*4);
    CP_WAIT(0); __syncthreads();          // G5 done
    chunk_fma(a0,a1,a2,a3, b1 + row*132, wsmL + 451*8 + cg*4);
  }
  // bias + gate stash
  {
    float4 bv = *(const float4*)(bsmL + cg*4);
    float4 g; g.x=a0+bv.x; g.y=a1+bv.y; g.z=a2+bv.z; g.w=a3+bv.w;
    *(float4*)(gsm + row*8 + cg*4) = g;
  }
  __syncthreads();
  // cell update: thread = (row r, unit-offset du); gate order i,f,g,o
  {
    const int r = tid >> 1, du = tid & 1;
    const float* gr = gsm + r*8;
    float ii = sigmf(gr[du]);
    float ff = sigmf(gr[2 + du]);
    float gg = tanhf(gr[4 + du]);
    float oo = sigmf(gr[6 + du]);
    float cv = ff*csmL[tid] + ii*gg;
    csmL[tid] = cv;
    float hv = oo*tanhf(cv);
    int gi = r*H_ + 2*cta + du;
    __stcg(&hout[gi], hv);
    if (histp) histp[gi] = hv;
  }
  __syncthreads();
}

// ------------------------- weight preload ------------------------------------
__device__ __forceinline__ void preload_w(
    float* dst, const float* __restrict__ Wih, const float* __restrict__ Whh,
    int KIN, int KTOT, int u0g, int tid)
{
  for (int i = tid; i < KTOT*8; i += NTHR) {
    int k = i >> 3, j = i & 7, gate = j >> 1, du = j & 1;
    int col = gate*256 + u0g + du;
    float v = (k < KIN) ? __ldg(&Wih[k*1024 + col]) : __ldg(&Whh[(k-KIN)*1024 + col]);
    dst[k*8 + j] = v;
  }
}

// ------------------------- reset (per launch) --------------------------------
__global__ void reset_kernel() { g_arrive = 0u; g_epoch = 0u; }

// ------------------------- main persistent kernel ----------------------------
__global__ void __launch_bounds__(NTHR, 1) main_kernel(
    const float* __restrict__ x,  const int* __restrict__ cc,
    const float* __restrict__ Wih1, const float* __restrict__ Whh1,
    const float* __restrict__ bih1, const float* __restrict__ bhh1,
    const float* __restrict__ Wih2, const float* __restrict__ Whh2,
    const float* __restrict__ bih2, const float* __restrict__ bhh2,
    const float* __restrict__ Wih3, const float* __restrict__ Whh3,
    const float* __restrict__ bih3, const float* __restrict__ bhh3,
    const float* __restrict__ Ww,   const float* __restrict__ bw)
{
  extern __shared__ float sm[];
  float* wsm1 = sm + OFF_W1;
  float* wsm2 = sm + OFF_W2;
  float* wsm3 = sm + OFF_W3;
  float* bsm  = sm + OFF_B;
  float* csm  = sm + OFF_C;      // [3][256]
  float* h1row= sm + OFF_HR;
  float* win  = sm + OFF_WIN;
  float* kap  = sm + OFF_KAP;
  float* Phi  = sm + OFF_PHI;
  int*   cidx = (int*)(sm + OFF_CIDX);

  const int tid = threadIdx.x;
  const int cta = blockIdx.x;
  const int u0g = 2*cta;
  const int brow = cta;          // window-phase batch row

  // ---- one-time preload: all weights for this CTA's 8 gate-columns ----
  preload_w(wsm1, Wih1, Whh1, 67,  323, u0g, tid);
  preload_w(wsm2, Wih2, Whh2, 323, 579, u0g, tid);
  preload_w(wsm3, Wih3, Whh3, 323, 579, u0g, tid);
  if (tid < 8) {
    int gate = tid >> 1, du = tid & 1, col = gate*256 + u0g + du;
    bsm[tid]      = __ldg(&bih1[col]) + __ldg(&bhh1[col]);
    bsm[8 + tid]  = __ldg(&bih2[col]) + __ldg(&bhh2[col]);
    bsm[16 + tid] = __ldg(&bih3[col]) + __ldg(&bhh3[col]);
  }
  { csm[tid]=0.f; csm[256+tid]=0.f; csm[512+tid]=0.f; }
  if (tid < 16) kap[tid] = 0.f;
  if (tid < 64) cidx[tid] = __ldg(&cc[brow*U_ + tid]);
  // zero h state, w = 1 (reference carry0)
  __stcg(&g_h1[0][brow*H_ + tid], 0.f);
  __stcg(&g_h2[0][brow*H_ + tid], 0.f);
  __stcg(&g_h3[0][brow*H_ + tid], 0.f);
  if (tid < 64) __stcg(&g_w[brow*A_ + tid], 1.0f);
  __syncthreads();

  unsigned ep = 1;
  gbar(ep++);

  for (int t = 0; t < T_; ++t) {
    const int p = t & 1;

    // ---- phase A: LSTM1  (x | w | h1_rec) ----
    lstm_phase<false>(sm, wsm1, bsm, csm,
                      t, cta, tid, x, g_h1[p], (const float*)0,
                      g_h1[1-p], (float*)0);
    gbar(ep++);

    // ---- phase B: attention window (CTA brow handles row brow) ----
    {
      const float* h1g = g_h1[1-p] + brow*H_;
      h1row[tid] = __ldcg(&h1g[tid]);
      __syncthreads();
      int j = tid >> 3, l = tid & 7;
      int jc = (j < 30) ? j : 0;
      float s = 0.f;
      for (int k = l; k < 256; k += 8) s = fmaf(h1row[k], __ldg(&Ww[k*30 + jc]), s);
      s += __shfl_xor_sync(0xffffffffu, s, 4);
      s += __shfl_xor_sync(0xffffffffu, s, 2);
      s += __shfl_xor_sync(0xffffffffu, s, 1);
      if (l == 0 && j < 30) win[j] = expf(s + __ldg(&bw[j]));
      __syncthreads();
      if (tid < KMIX) kap[tid] += 0.1f * win[20 + tid];
      __syncthreads();
      if (tid < U_) {
        float u = (float)tid;
        float ph = 0.f;
        #pragma unroll
        for (int k = 0; k < KMIX; ++k) {
          float d = kap[k] - u;
          ph += win[k] * expf(-win[10 + k] * d * d);
        }
        Phi[tid] = ph;
      }
      __syncthreads();
      if (tid < A_) {
        float s2 = 0.f;
        #pragma unroll 4
        for (int u = 0; u < U_; ++u)
          if (cidx[u] == tid) s2 += Phi[u];
        __stcg(&g_w[brow*A_ + tid], s2);
      }
    }
    gbar(ep++);

    // ---- phase C: LSTM2  (x | w | h1_new | h2_rec) ----
    lstm_phase<true>(sm, wsm2, bsm + 8, csm + 256,
                     t, cta, tid, x, g_h1[1-p], g_h2[p],
                     g_h2[1-p], (float*)0);
    gbar(ep++);

    // ---- phase D: LSTM3  (x | w | h2_new | h3_rec), + history ----
    lstm_phase<true>(sm, wsm3, bsm + 16, csm + 512,
                     t, cta, tid, x, g_h2[1-p], g_h3[p],
                     g_h3[1-p], &g_hist[(size_t)t * B_ * H_]);
    // no barrier needed: D(t) overlaps only A(t+1), disjoint buffers.
  }
}

// ------------------------- MDN heads -----------------------------------------
#define PHEAD 8
__global__ void __launch_bounds__(128) heads_kernel(
    const float* __restrict__ We,   const float* __restrict__ be,
    const float* __restrict__ Wpi,  const float* __restrict__ bpi,
    const float* __restrict__ Wmu1, const float* __restrict__ bmu1,
    const float* __restrict__ Wmu2, const float* __restrict__ bmu2,
    const float* __restrict__ Ws1,  const float* __restrict__ bs1,
    const float* __restrict__ Ws2,  const float* __restrict__ bs2,
    const float* __restrict__ Wrho, const float* __restrict__ brho,
    float* __restrict__ out)
{
  __shared__ float hs[PHEAD*H_];
  __shared__ float raw[PHEAD][128];
  __shared__ float stat[PHEAD][2];
  const int p0  = blockIdx.x * PHEAD;
  const int tid = threadIdx.x;

  for (int i = tid; i < PHEAD*H_; i += 128)
    hs[i] = g_hist[(size_t)p0*H_ + i];
  __syncthreads();

  const int j = tid;
  if (j < 121) {
    const float* W; int stride, cs; float bias;
    if (j == 0)      { W = We;   stride = 1;  cs = 0;     bias = __ldg(&be[0]);    }
    else if (j < 21) { W = Wpi;  stride = 20; cs = j-1;   bias = __ldg(&bpi[cs]);  }
    else if (j < 41) { W = Wmu1; stride = 20; cs = j-21;  bias = __ldg(&bmu1[cs]); }
    else if (j < 61) { W = Wmu2; stride = 20; cs = j-41;  bias = __ldg(&bmu2[cs]); }
    else if (j < 81) { W = Ws1;  stride = 20; cs = j-61;  bias = __ldg(&bs1[cs]);  }
    else if (j < 101){ W = Ws2;  stride = 20; cs = j-81;  bias = __ldg(&bs2[cs]);  }
    else             { W = Wrho; stride = 20; cs = j-101; bias = __ldg(&brho[cs]); }
    float acc[PHEAD];
    #pragma unroll
    for (int r = 0; r < PHEAD; ++r) acc[r] = 0.f;
    #pragma unroll 4
    for (int k = 0; k < H_; ++k) {
      float wv = __ldg(&W[k*stride + cs]);
      #pragma unroll
      for (int r = 0; r < PHEAD; ++r) acc[r] = fmaf(hs[r*H_ + k], wv, acc[r]);
    }
    #pragma unroll
    for (int r = 0; r < PHEAD; ++r) raw[r][j] = acc[r] + bias;
  }
  __syncthreads();

  if (tid < PHEAD) {
    float m = -1e30f;
    for (int g = 1; g < 21; ++g) m = fmaxf(m, raw[tid][g]);
    float s = 0.f;
    for (int g = 1; g < 21; ++g) s += expf(raw[tid][g] - m);
    stat[tid][0] = m; stat[tid][1] = s;
  }
  __syncthreads();

  if (j < 121) {
    const int blk = (j == 0) ? -1 : (j-1)/20;
    const int g   = (j == 0) ? 0  : (j-1)%20;
    #pragma unroll
    for (int r = 0; r < PHEAD; ++r) {
      size_t p = (size_t)(p0 + r);
      float v = raw[r][j];
      if (j == 0) {
        out[p] = 1.0f / (1.0f + expf(v));
      } else {
        float o;
        if      (blk == 0) o = expf(v - stat[r][0]) / stat[r][1];
        else if (blk <= 2) o = v;
        else if (blk <= 4) o = expf(v);
        else               o = tanhf(v);
        out[(size_t)TB_ + (size_t)blk * (TB_*(size_t)GMIX) + p*GMIX + g] = o;
      }
    }
  }
}

// ------------------------- launch --------------------------------------------
extern "C" void kernel_launch(void* const* d_in, const int* in_sizes, int n_in,
                              void* d_out, int out_size) {
  const float* x    = (const float*)d_in[0];
  const int*   cc   = (const int*)  d_in[1];
  const float* Wih1 = (const float*)d_in[2];
  const float* Whh1 = (const float*)d_in[3];
  const float* bih1 = (const float*)d_in[4];
  const float* bhh1 = (const float*)d_in[5];
  const float* Wih2 = (const float*)d_in[6];
  const float* Whh2 = (const float*)d_in[7];
  const float* bih2 = (const float*)d_in[8];
  const float* bhh2 = (const float*)d_in[9];
  const float* Wih3 = (const float*)d_in[10];
  const float* Whh3 = (const float*)d_in[11];
  const float* bih3 = (const float*)d_in[12];
  const float* bhh3 = (const float*)d_in[13];
  const float* Ww   = (const float*)d_in[14];
  const float* bw   = (const float*)d_in[15];
  const float* We   = (const float*)d_in[16];
  const float* be   = (const float*)d_in[17];
  const float* Wpi  = (const float*)d_in[18];
  const float* bpi  = (const float*)d_in[19];
  const float* Wmu1 = (const float*)d_in[20];
  const float* bmu1 = (const float*)d_in[21];
  const float* Wmu2 = (const float*)d_in[22];
  const float* bmu2 = (const float*)d_in[23];
  const float* Ws1  = (const float*)d_in[24];
  const float* bs1  = (const float*)d_in[25];
  const float* Ws2  = (const float*)d_in[26];
  const float* bs2  = (const float*)d_in[27];
  const float* Wrho = (const float*)d_in[28];
  const float* brho = (const float*)d_in[29];
  float* out = (float*)d_out;

  cudaFuncSetAttribute(main_kernel, cudaFuncAttributeMaxDynamicSharedMemorySize, SMEM_BYTES);

  reset_kernel<<<1, 1>>>();
  main_kernel<<<NCTA, NTHR, SMEM_BYTES>>>(
      x, cc, Wih1, Whh1, bih1, bhh1, Wih2, Whh2, bih2, bhh2,
      Wih3, Whh3, bih3, bhh3, Ww, bw);
  heads_kernel<<<TB_/PHEAD, 128>>>(
      We, be, Wpi, bpi, Wmu1, bmu1, Wmu2, bmu2,
      Ws1, bs1, Ws2, bs2, Wrho, brho, out);
}

// round 10
// speedup vs baseline: 4.5752x; 1.0614x over previous
#include <cuda_runtime.h>
#include <cuda_bf16.h>
#include <cstdint>

#define NCTA 128
#define NTHR 256
#define B_   128
#define T_   800
#define H_   256
#define U_   64
#define KMIX 10
#define GMIX 20
#define A_   64
#define TB_  (T_*B_)

// smem layout (float offsets)
#define OFF_W1   0        // [323*8]
#define OFF_W2   2584     // [579*8]
#define OFF_W3   7216     // [579*8]
#define OFF_B    11848    // [24]
#define OFF_BW   11872    // [128*68]
#define OFF_H0   20576    // [128*132]
#define OFF_H1   37472    // [128*132]
#define OFF_G    54368    // [128*8]
#define OFF_C    55392    // [3*256]
#define OFF_HR   56160    // [256]
#define OFF_WIN  56416    // [32]
#define OFF_KAP  56448    // [16]
#define OFF_PHI  56464    // [64]
#define OFF_CIDX 56528    // [64] ints
#define SMEM_FLOATS 56592
#define SMEM_BYTES (SMEM_FLOATS*4)

// per-phase weight smem sub-layout (pair-interleaved):
//   [0,24)        x rows: k*8 + j                (k = 0..2, scalar)
//   [24,536)      w segment: 32 pair-rows of 16  (pair p, col j, par o -> 24 + p*16 + j*2 + o)
//   [536 + c*1024, ...)  h chunk c: 64 pair-rows of 16

// ------------------------- persistent device state ---------------------------
__device__ __align__(16) float g_h1[2][B_*H_];
__device__ __align__(16) float g_h2[2][B_*H_];
__device__ __align__(16) float g_h3[2][B_*H_];
__device__ __align__(16) float g_w[B_*A_];
__device__ __align__(16) float g_hist[(size_t)T_*B_*H_];
__device__ unsigned g_arrive;
__device__ volatile unsigned g_epoch;

__device__ __forceinline__ float sigmf(float x) { return 1.0f/(1.0f+expf(-x)); }

// ------------------------- f32x2 helpers --------------------------------------
__device__ __forceinline__ void fma2(unsigned long long& acc,
                                     unsigned long long a, unsigned long long b) {
  asm("fma.rn.f32x2 %0, %1, %2, %3;" : "=l"(acc) : "l"(a), "l"(b), "l"(acc));
}
__device__ __forceinline__ unsigned long long packf2(float lo, float hi) {
  unsigned long long r;
  asm("mov.b64 %0, {%1, %2};" : "=l"(r) : "f"(lo), "f"(hi));
  return r;
}
__device__ __forceinline__ float hsumf2(unsigned long long v) {
  float lo, hi;
  asm("mov.b64 {%0, %1}, %2;" : "=f"(lo), "=f"(hi) : "l"(v));
  return lo + hi;
}

// ------------------------- cp.async helpers ----------------------------------
__device__ __forceinline__ unsigned smem_u32(const void* p) {
  return (unsigned)__cvta_generic_to_shared(p);
}
__device__ __forceinline__ void cpa16(unsigned dst, const float* src) {
  asm volatile("cp.async.cg.shared.global [%0], [%1], 16;\n" :: "r"(dst), "l"(src));
}
#define CP_COMMIT  asm volatile("cp.async.commit_group;\n")
#define CP_WAIT(n) asm volatile("cp.async.wait_group %0;\n" :: "n"(n))

// ------------------------- grid barrier (epoch counting) ---------------------
__device__ __forceinline__ void gbar(unsigned e) {
  __syncthreads();
  if (threadIdx.x == 0) {
    __threadfence();
    unsigned v = atomicAdd(&g_arrive, 1u);
    if (v == e*(unsigned)NCTA - 1u) {
      atomicExch((unsigned*)&g_epoch, e);
    } else {
      while (g_epoch < e) { __nanosleep(32); }
    }
    __threadfence();
  }
  __syncthreads();
}

// ------------------------- staging -------------------------------------------
// stage one 128-wide K chunk of an h-matrix [128 rows x 256] into buf[128][132]
__device__ __forceinline__ void stage_h(float* buf, const float* src, int k0, int tid) {
  #pragma unroll
  for (int n = 0; n < 16; ++n) {
    int i = tid + n*NTHR;
    int r = i >> 5, kq = i & 31;
    cpa16(smem_u32(buf + r*132 + kq*4), src + r*256 + k0 + kq*4);
  }
}
// stage attention-window vector w [128 rows x 64] into bufW[128][68]
__device__ __forceinline__ void stage_w(float* buf, int tid) {
  #pragma unroll
  for (int n = 0; n < 8; ++n) {
    int i = tid + n*NTHR;
    int r = i >> 4, kq = i & 15;
    cpa16(smem_u32(buf + r*68 + kq*4), g_w + r*64 + kq*4);
  }
}

// ------------------------- paired FMA chunk (NP k-pairs) ----------------------
template<int NP>
__device__ __forceinline__ void chunk_fma2(
    unsigned long long& q0, unsigned long long& q1,
    unsigned long long& q2, unsigned long long& q3,
    const float* __restrict__ ar,   // act row ptr (pairs contiguous)
    const float* __restrict__ wk)   // pair-row base + cg*8
{
  #pragma unroll 4
  for (int p = 0; p < NP; ++p) {
    unsigned long long av = *(const unsigned long long*)(ar + 2*p);
    ulonglong2 w01 = *(const ulonglong2*)(wk + p*16);
    ulonglong2 w23 = *(const ulonglong2*)(wk + p*16 + 4);
    fma2(q0, av, w01.x); fma2(q1, av, w01.y);
    fma2(q2, av, w23.x); fma2(q3, av, w23.y);
  }
}

// ------------------------- LSTM phase ----------------------------------------
// CTA owns units {2*cta, 2*cta+1} x all 128 rows. Virtual input:
// [x(3) | w(64) | hA(256) | hB(256 iff HASB)], weights pair-interleaved in wsmL.
// col order per k: [i0,i1,f0,f1,g0,g1,o0,o1]. STAGEW: refresh bufW from g_w.
template<bool HASB, bool STAGEW>
__device__ __forceinline__ void lstm_phase(
    float* __restrict__ sm,
    const float* __restrict__ wsmL, const float* __restrict__ bsmL,
    float* __restrict__ csmL,
    int t, int cta, int tid,
    const float* __restrict__ x,
    const float* __restrict__ hA, const float* __restrict__ hB,
    float* __restrict__ hout, float* __restrict__ histp)
{
  float* bufW = sm + OFF_BW;
  float* b0   = sm + OFF_H0;
  float* b1   = sm + OFF_H1;
  float* gsm  = sm + OFF_G;
  const int row = tid >> 1, cg = tid & 1;

  if (STAGEW) { stage_w(bufW, tid); CP_COMMIT; }   // Gw
  stage_h(b0, hA, 0, tid); CP_COMMIT;              // Ga

  // x part (k = 0..2) into scalar partials, then packed into accumulators
  unsigned long long q0, q1, q2, q3;
  {
    const float* xr = x + (row*T_ + t)*3;
    float xv0=__ldg(xr), xv1=__ldg(xr+1), xv2=__ldg(xr+2);
    const float* wk = wsmL + cg*4;
    float4 w0=*(const float4*)(wk), w1=*(const float4*)(wk+8), w2=*(const float4*)(wk+16);
    float a0 = xv0*w0.x + xv1*w1.x + xv2*w2.x;
    float a1 = xv0*w0.y + xv1*w1.y + xv2*w2.y;
    float a2 = xv0*w0.z + xv1*w1.z + xv2*w2.z;
    float a3 = xv0*w0.w + xv1*w1.w + xv2*w2.w;
    q0 = packf2(a0, 0.f); q1 = packf2(a1, 0.f);
    q2 = packf2(a2, 0.f); q3 = packf2(a3, 0.f);
  }
  if (STAGEW) { CP_WAIT(1); __syncthreads(); }     // Gw done (Ga may be in flight)
  // w segment (k = 3..66), 32 pairs; bufW valid (staged now or left from prior phase)
  chunk_fma2<32>(q0,q1,q2,q3, bufW + row*68, wsmL + 24 + cg*8);

  stage_h(b1, hA, 128, tid); CP_COMMIT;            // Gb
  CP_WAIT(1); __syncthreads();                     // Ga done (b0 = hA[0:128))
  chunk_fma2<64>(q0,q1,q2,q3, b0 + row*132, wsmL + 536 + cg*8);
  __syncthreads();                                 // all done reading b0
  if (HASB) { stage_h(b0, hB, 0, tid); CP_COMMIT; }        // Gc
  CP_WAIT(HASB ? 1 : 0); __syncthreads();          // Gb done (b1 = hA[128:256))
  chunk_fma2<64>(q0,q1,q2,q3, b1 + row*132, wsmL + 536 + 1024 + cg*8);
  if (HASB) {
    __syncthreads();                               // done reading b1
    stage_h(b1, hB, 128, tid); CP_COMMIT;          // Gd
    CP_WAIT(1); __syncthreads();                   // Gc done (b0 = hB[0:128))
    chunk_fma2<64>(q0,q1,q2,q3, b0 + row*132, wsmL + 536 + 2048 + cg*8);
    CP_WAIT(0); __syncthreads();                   // Gd done (b1 = hB[128:256))
    chunk_fma2<64>(q0,q1,q2,q3, b1 + row*132, wsmL + 536 + 3072 + cg*8);
  }
  // bias + gate stash
  {
    float4 bv = *(const float4*)(bsmL + cg*4);
    float4 g;
    g.x = hsumf2(q0) + bv.x; g.y = hsumf2(q1) + bv.y;
    g.z = hsumf2(q2) + bv.z; g.w = hsumf2(q3) + bv.w;
    *(float4*)(gsm + row*8 + cg*4) = g;
  }
  __syncthreads();
  // cell update: thread = (row r, unit-offset du); gate order i,f,g,o
  {
    const int r = tid >> 1, du = tid & 1;
    const float* gr = gsm + r*8;
    float ii = sigmf(gr[du]);
    float ff = sigmf(gr[2 + du]);
    float gg = tanhf(gr[4 + du]);
    float oo = sigmf(gr[6 + du]);
    float cv = ff*csmL[tid] + ii*gg;
    csmL[tid] = cv;
    float hv = oo*tanhf(cv);
    int gi = r*H_ + 2*cta + du;
    __stcg(&hout[gi], hv);
    if (histp) histp[gi] = hv;
  }
  __syncthreads();
}

// ------------------------- weight preload (pair-interleaved) ------------------
__device__ __forceinline__ void preload_w(
    float* dst, const float* __restrict__ Wih, const float* __restrict__ Whh,
    int KIN, int KTOT, int u0g, int tid)
{
  for (int i = tid; i < KTOT*8; i += NTHR) {
    int k = i >> 3, j = i & 7, gate = j >> 1, du = j & 1;
    int col = gate*256 + u0g + du;
    float v = (k < KIN) ? __ldg(&Wih[k*1024 + col]) : __ldg(&Whh[(k-KIN)*1024 + col]);
    int idx;
    if (k < 3) {
      idx = k*8 + j;
    } else if (k < 67) {
      int kk = k - 3;
      idx = 24 + (kk >> 1)*16 + j*2 + (kk & 1);
    } else {
      int kk = k - 67;
      int c = kk >> 7, r = kk & 127;
      idx = 536 + c*1024 + (r >> 1)*16 + j*2 + (r & 1);
    }
    dst[idx] = v;
  }
}

// ------------------------- reset (per launch) --------------------------------
__global__ void reset_kernel() { g_arrive = 0u; g_epoch = 0u; }

// ------------------------- main persistent kernel ----------------------------
__global__ void __launch_bounds__(NTHR, 1) main_kernel(
    const float* __restrict__ x,  const int* __restrict__ cc,
    const float* __restrict__ Wih1, const float* __restrict__ Whh1,
    const float* __restrict__ bih1, const float* __restrict__ bhh1,
    const float* __restrict__ Wih2, const float* __restrict__ Whh2,
    const float* __restrict__ bih2, const float* __restrict__ bhh2,
    const float* __restrict__ Wih3, const float* __restrict__ Whh3,
    const float* __restrict__ bih3, const float* __restrict__ bhh3,
    const float* __restrict__ Ww,   const float* __restrict__ bw)
{
  extern __shared__ float sm[];
  float* wsm1 = sm + OFF_W1;
  float* wsm2 = sm + OFF_W2;
  float* wsm3 = sm + OFF_W3;
  float* bsm  = sm + OFF_B;
  float* bufW = sm + OFF_BW;
  float* csm  = sm + OFF_C;      // [3][256]
  float* h1row= sm + OFF_HR;
  float* win  = sm + OFF_WIN;
  float* kap  = sm + OFF_KAP;
  float* Phi  = sm + OFF_PHI;
  int*   cidx = (int*)(sm + OFF_CIDX);

  const int tid = threadIdx.x;
  const int cta = blockIdx.x;
  const int u0g = 2*cta;
  const int brow = cta;          // window-phase batch row

  // ---- one-time preload: all weights for this CTA's 8 gate-columns ----
  preload_w(wsm1, Wih1, Whh1, 67,  323, u0g, tid);
  preload_w(wsm2, Wih2, Whh2, 323, 579, u0g, tid);
  preload_w(wsm3, Wih3, Whh3, 323, 579, u0g, tid);
  if (tid < 8) {
    int gate = tid >> 1, du = tid & 1, col = gate*256 + u0g + du;
    bsm[tid]      = __ldg(&bih1[col]) + __ldg(&bhh1[col]);
    bsm[8 + tid]  = __ldg(&bih2[col]) + __ldg(&bhh2[col]);
    bsm[16 + tid] = __ldg(&bih3[col]) + __ldg(&bhh3[col]);
  }
  { csm[tid]=0.f; csm[256+tid]=0.f; csm[512+tid]=0.f; }
  if (tid < 16) kap[tid] = 0.f;
  if (tid < 64) cidx[tid] = __ldg(&cc[brow*U_ + tid]);
  // seed bufW with initial w = 1 (phase A at t=0 reuses it without staging)
  for (int i = tid; i < 128*64; i += NTHR) bufW[(i >> 6)*68 + (i & 63)] = 1.0f;
  // zero h state, w = 1 (reference carry0)
  __stcg(&g_h1[0][brow*H_ + tid], 0.f);
  __stcg(&g_h2[0][brow*H_ + tid], 0.f);
  __stcg(&g_h3[0][brow*H_ + tid], 0.f);
  if (tid < 64) __stcg(&g_w[brow*A_ + tid], 1.0f);
  __syncthreads();

  unsigned ep = 1;
  gbar(ep++);

  for (int t = 0; t < T_; ++t) {
    const int p = t & 1;

    // ---- phase A: LSTM1  (x | w(t-1) from bufW | h1_rec) ----
    lstm_phase<false,false>(sm, wsm1, bsm, csm,
                            t, cta, tid, x, g_h1[p], (const float*)0,
                            g_h1[1-p], (float*)0);
    gbar(ep++);

    // ---- phase B: attention window (CTA brow handles row brow) ----
    {
      const float* h1g = g_h1[1-p] + brow*H_;
      h1row[tid] = __ldcg(&h1g[tid]);
      __syncthreads();
      int j = tid >> 3, l = tid & 7;
      int jc = (j < 30) ? j : 0;
      float s = 0.f;
      for (int k = l; k < 256; k += 8) s = fmaf(h1row[k], __ldg(&Ww[k*30 + jc]), s);
      s += __shfl_xor_sync(0xffffffffu, s, 4);
      s += __shfl_xor_sync(0xffffffffu, s, 2);
      s += __shfl_xor_sync(0xffffffffu, s, 1);
      if (l == 0 && j < 30) win[j] = expf(s + __ldg(&bw[j]));
      __syncthreads();
      if (tid < KMIX) kap[tid] += 0.1f * win[20 + tid];
      __syncthreads();
      if (tid < U_) {
        float u = (float)tid;
        float ph = 0.f;
        #pragma unroll
        for (int k = 0; k < KMIX; ++k) {
          float d = kap[k] - u;
          ph += win[k] * expf(-win[10 + k] * d * d);
        }
        Phi[tid] = ph;
      }
      __syncthreads();
      if (tid < A_) {
        float s2 = 0.f;
        #pragma unroll 4
        for (int u = 0; u < U_; ++u)
          if (cidx[u] == tid) s2 += Phi[u];
        __stcg(&g_w[brow*A_ + tid], s2);
      }
    }
    gbar(ep++);

    // ---- phase C: LSTM2  (x | w_new staged | h1_new | h2_rec) ----
    lstm_phase<true,true>(sm, wsm2, bsm + 8, csm + 256,
                          t, cta, tid, x, g_h1[1-p], g_h2[p],
                          g_h2[1-p], (float*)0);
    gbar(ep++);

    // ---- phase D: LSTM3  (x | w_new from bufW | h2_new | h3_rec), + history ----
    lstm_phase<true,false>(sm, wsm3, bsm + 16, csm + 512,
                           t, cta, tid, x, g_h2[1-p], g_h3[p],
                           g_h3[1-p], &g_hist[(size_t)t * B_ * H_]);
    // no barrier needed: D(t) overlaps only A(t+1), disjoint buffers; bufW
    // holds w(t) which is exactly what A(t+1) must consume.
  }
}

// ------------------------- MDN heads -----------------------------------------
#define PHEAD 8
__global__ void __launch_bounds__(128) heads_kernel(
    const float* __restrict__ We,   const float* __restrict__ be,
    const float* __restrict__ Wpi,  const float* __restrict__ bpi,
    const float* __restrict__ Wmu1, const float* __restrict__ bmu1,
    const float* __restrict__ Wmu2, const float* __restrict__ bmu2,
    const float* __restrict__ Ws1,  const float* __restrict__ bs1,
    const float* __restrict__ Ws2,  const float* __restrict__ bs2,
    const float* __restrict__ Wrho, const float* __restrict__ brho,
    float* __restrict__ out)
{
  __shared__ float hs[PHEAD*H_];
  __shared__ float raw[PHEAD][128];
  __shared__ float stat[PHEAD][2];
  const int p0  = blockIdx.x * PHEAD;
  const int tid = threadIdx.x;

  for (int i = tid; i < PHEAD*H_; i += 128)
    hs[i] = g_hist[(size_t)p0*H_ + i];
  __syncthreads();

  const int j = tid;
  if (j < 121) {
    const float* W; int stride, cs; float bias;
    if (j == 0)      { W = We;   stride = 1;  cs = 0;     bias = __ldg(&be[0]);    }
    else if (j < 21) { W = Wpi;  stride = 20; cs = j-1;   bias = __ldg(&bpi[cs]);  }
    else if (j < 41) { W = Wmu1; stride = 20; cs = j-21;  bias = __ldg(&bmu1[cs]); }
    else if (j < 61) { W = Wmu2; stride = 20; cs = j-41;  bias = __ldg(&bmu2[cs]); }
    else if (j < 81) { W = Ws1;  stride = 20; cs = j-61;  bias = __ldg(&bs1[cs]);  }
    else if (j < 101){ W = Ws2;  stride = 20; cs = j-81;  bias = __ldg(&bs2[cs]);  }
    else             { W = Wrho; stride = 20; cs = j-101; bias = __ldg(&brho[cs]); }
    float acc[PHEAD];
    #pragma unroll
    for (int r = 0; r < PHEAD; ++r) acc[r] = 0.f;
    #pragma unroll 4
    for (int k = 0; k < H_; ++k) {
      float wv = __ldg(&W[k*stride + cs]);
      #pragma unroll
      for (int r = 0; r < PHEAD; ++r) acc[r] = fmaf(hs[r*H_ + k], wv, acc[r]);
    }
    #pragma unroll
    for (int r = 0; r < PHEAD; ++r) raw[r][j] = acc[r] + bias;
  }
  __syncthreads();

  if (tid < PHEAD) {
    float m = -1e30f;
    for (int g = 1; g < 21; ++g) m = fmaxf(m, raw[tid][g]);
    float s = 0.f;
    for (int g = 1; g < 21; ++g) s += expf(raw[tid][g] - m);
    stat[tid][0] = m; stat[tid][1] = s;
  }
  __syncthreads();

  if (j < 121) {
    const int blk = (j == 0) ? -1 : (j-1)/20;
    const int g   = (j == 0) ? 0  : (j-1)%20;
    #pragma unroll
    for (int r = 0; r < PHEAD; ++r) {
      size_t p = (size_t)(p0 + r);
      float v = raw[r][j];
      if (j == 0) {
        out[p] = 1.0f / (1.0f + expf(v));
      } else {
        float o;
        if      (blk == 0) o = expf(v - stat[r][0]) / stat[r][1];
        else if (blk <= 2) o = v;
        else if (blk <= 4) o = expf(v);
        else               o = tanhf(v);
        out[(size_t)TB_ + (size_t)blk * (TB_*(size_t)GMIX) + p*GMIX + g] = o;
      }
    }
  }
}

// ------------------------- launch --------------------------------------------
extern "C" void kernel_launch(void* const* d_in, const int* in_sizes, int n_in,
                              void* d_out, int out_size) {
  const float* x    = (const float*)d_in[0];
  const int*   cc   = (const int*)  d_in[1];
  const float* Wih1 = (const float*)d_in[2];
  const float* Whh1 = (const float*)d_in[3];
  const float* bih1 = (const float*)d_in[4];
  const float* bhh1 = (const float*)d_in[5];
  const float* Wih2 = (const float*)d_in[6];
  const float* Whh2 = (const float*)d_in[7];
  const float* bih2 = (const float*)d_in[8];
  const float* bhh2 = (const float*)d_in[9];
  const float* Wih3 = (const float*)d_in[10];
  const float* Whh3 = (const float*)d_in[11];
  const float* bih3 = (const float*)d_in[12];
  const float* bhh3 = (const float*)d_in[13];
  const float* Ww   = (const float*)d_in[14];
  const float* bw   = (const float*)d_in[15];
  const float* We   = (const float*)d_in[16];
  const float* be   = (const float*)d_in[17];
  const float* Wpi  = (const float*)d_in[18];
  const float* bpi  = (const float*)d_in[19];
  const float* Wmu1 = (const float*)d_in[20];
  const float* bmu1 = (const float*)d_in[21];
  const float* Wmu2 = (const float*)d_in[22];
  const float* bmu2 = (const float*)d_in[23];
  const float* Ws1  = (const float*)d_in[24];
  const float* bs1  = (const float*)d_in[25];
  const float* Ws2  = (const float*)d_in[26];
  const float* bs2  = (const float*)d_in[27];
  const float* Wrho = (const float*)d_in[28];
  const float* brho = (const float*)d_in[29];
  float* out = (float*)d_out;

  cudaFuncSetAttribute(main_kernel, cudaFuncAttributeMaxDynamicSharedMemorySize, SMEM_BYTES);

  reset_kernel<<<1, 1>>>();
  main_kernel<<<NCTA, NTHR, SMEM_BYTES>>>(
      x, cc, Wih1, Whh1, bih1, bhh1, Wih2, Whh2, bih2, bhh2,
      Wih3, Whh3, bih3, bhh3, Ww, bw);
  heads_kernel<<<TB_/PHEAD, 128>>>(
      We, be, Wpi, bpi, Wmu1, bmu1, Wmu2, bmu2,
      Ws1, bs1, Ws2, bs2, Wrho, brho, out);
}